// round 8
// baseline (speedup 1.0000x reference)
#include <cuda_runtime.h>
#include <cstdint>

#define NROWS 65536
#define DDIM 512
#define NUM_LABELS 512
#define NUM_DEMOG 4
#define NGROUP (NUM_LABELS * NUM_DEMOG)

#define GRID_STREAM 444          /* 148 SMs x 3 CTAs: one wave guaranteed */
#define TS 256                   /* threads per CTA */
#define CHUNK 148                /* rows per CTA (444*148 = 65712 >= 65536) */
#define BR 8                     /* rows per batch */
#define NB 4                     /* ring depth in batches */
#define CHUNK_PAD 152            /* ceil(148/8)*8 */
#define NBATCH 19                /* CHUNK_PAD / BR */
#define ROWB 2048                /* bytes per row */

// -------- persistent device state (statically zero; self-cleaning) --------
__device__ int    g_cnt[NGROUP];          // zeroed by pass2 after read
__device__ int    g_off[NGROUP + 1];      // overwritten each run
__device__ int    g_cursor[NGROUP];       // overwritten each run
__device__ int    g_sorted[NROWS];        // overwritten each run
__device__ int    g_seg_sorted[NROWS];    // overwritten each run
__device__ float4 g_sums4[NGROUP * (DDIM / 4)];  // zeroed by pass2 after read
__device__ float  g_ssq[NGROUP];          // zeroed by pass2 after read
__device__ double g_gm[NGROUP];           // overwritten each run
__device__ int    g_bar[4];               // grid-barrier counters (reset by finalize)
__device__ int    g_fin_done;             // ticket (reset by finalize)

// ---------------- cp.async helpers ----------------
__device__ __forceinline__ void cp_async16(uint32_t dst, const float* src) {
    asm volatile("cp.async.cg.shared.global [%0], [%1], 16;" :: "r"(dst), "l"(src));
}
__device__ __forceinline__ void cp_commit() { asm volatile("cp.async.commit_group;" ::: "memory"); }
__device__ __forceinline__ void cp_wait0() { asm volatile("cp.async.wait_group 0;" ::: "memory"); }
__device__ __forceinline__ void cp_wait1() { asm volatile("cp.async.wait_group 1;" ::: "memory"); }
__device__ __forceinline__ void cp_wait2() { asm volatile("cp.async.wait_group 2;" ::: "memory"); }

// ---------------- grid barrier (all 444 CTAs resident => safe) ----------------
__device__ __forceinline__ void grid_bar(int idx) {
    __syncthreads();
    if (threadIdx.x == 0) {
        __threadfence();
        int v = atomicAdd(&g_bar[idx], 1) + 1;
        if (v < GRID_STREAM) {
            while (*(volatile int*)&g_bar[idx] < GRID_STREAM) __nanosleep(64);
        }
    }
    __syncthreads();
    __threadfence();   // acquire side
}

// ===== the one kernel: hist -> scan -> scatter -> stream -> pass2 -> finalize =====
extern "C" __global__ void __launch_bounds__(TS, 3) k_all(const float* __restrict__ feats,
                                                          const void* __restrict__ labels,
                                                          const void* __restrict__ demog,
                                                          float* __restrict__ out) {
    extern __shared__ __align__(16) char sm[];
    float* ring = (float*)sm;                                   // 64 KB
    int*   sidx = (int*)(sm + NB * BR * ROWB);                  // CHUNK_PAD ints
    int*   sseg = sidx + CHUNK_PAD;                             // CHUNK_PAD ints
    int*   scr  = sseg + CHUNK_PAD;                             // 16 ints scratch

    int bid = blockIdx.x, t = threadIdx.x;
    int lane = t & 31;
    int lo = bid * CHUNK;

    // ---- phase 0: dtype detect (per-CTA, cheap) + own-rows hist ----
    if (t == 0) {
        const int* lr = (const int*)labels;
        int nz = 0;
        for (int k = 1; k < 64; k += 2) nz += (lr[k] != 0);
        scr[15] = (nz == 0) ? 1 : 0;     // is64
    }
    __syncthreads();
    int is64 = scr[15];

    int myseg = -1;
    if (t < CHUNK && lo + t < NROWS) {
        int i = lo + t;
        int lab = is64 ? (int)((const long long*)labels)[i] : ((const int*)labels)[i];
        int dem = is64 ? (int)((const long long*)demog)[i]  : ((const int*)demog)[i];
        myseg = dem * NUM_LABELS + lab;
        atomicAdd(&g_cnt[myseg], 1);
    }

    grid_bar(0);

    // ---- phase 1: CTA 0 scans 2048 counts (8 per thread) ----
    if (bid == 0) {
        int base = t * 8;
        int c[8], pre[8], s = 0;
        #pragma unroll
        for (int j = 0; j < 8; ++j) c[j] = g_cnt[base + j];
        #pragma unroll
        for (int j = 0; j < 8; ++j) { pre[j] = s; s += c[j]; }
        int v = s;
        #pragma unroll
        for (int d = 1; d < 32; d <<= 1) {
            int u = __shfl_up_sync(0xffffffffu, v, d);
            if (lane >= d) v += u;
        }
        int w = t >> 5;
        if (lane == 31) scr[w] = v;      // 8 warp totals
        __syncthreads();
        if (t == 0) {
            int run = 0;
            #pragma unroll
            for (int j = 0; j < 8; ++j) { int x = scr[j]; scr[j] = run; run += x; }
        }
        __syncthreads();
        int excl = (v - s) + scr[w];
        #pragma unroll
        for (int j = 0; j < 8; ++j) {
            g_off[base + j]    = excl + pre[j];
            g_cursor[base + j] = excl + pre[j];
        }
        if (t == 255) g_off[NGROUP] = excl + s;
    }

    grid_bar(1);

    // ---- phase 2: scatter own rows into sorted order ----
    if (myseg >= 0) {
        int pos = atomicAdd(&g_cursor[myseg], 1);
        g_sorted[pos] = lo + t;
        g_seg_sorted[pos] = myseg;
    }

    grid_bar(2);

    // ---- phase 3: stream this CTA's chunk of the sorted order ----
    int c128 = t & 127;     // column lane
    int h = t >> 7;         // row parity
    for (int i = t; i < CHUNK_PAD; i += TS) {
        int gi = lo + i;
        if (i < CHUNK && gi < NROWS) {
            sidx[i] = g_sorted[gi];
            sseg[i] = g_seg_sorted[gi];
        } else {
            sidx[i] = 0;
            sseg[i] = -1;
        }
    }
    __syncthreads();

    uint32_t ring_base = (uint32_t)__cvta_generic_to_shared(ring) + (uint32_t)c128 * 16u;
    const float* fbase = feats + (c128 << 2);

    #pragma unroll
    for (int p = 0; p < 3; ++p) {
        #pragma unroll
        for (int rr = 0; rr < BR / 2; ++rr) {
            int ri = rr * 2 + h;
            const float* src = fbase + ((size_t)sidx[p * BR + ri] << 9);
            cp_async16(ring_base + (uint32_t)((p & (NB - 1)) * BR + ri) * ROWB, src);
        }
        cp_commit();
    }

    float4 acc = make_float4(0.f, 0.f, 0.f, 0.f);
    float  ssq = 0.f;
    int    cur = -1;

    for (int b = 0; b < NBATCH; ++b) {
        int k = NBATCH - 1 - b;
        if (k >= 2) cp_wait2(); else if (k == 1) cp_wait1(); else cp_wait0();

        const float* bp = ring + (size_t)((b & (NB - 1)) * BR) * DDIM + (c128 << 2);
        #pragma unroll
        for (int rr = 0; rr < BR / 2; ++rr) {
            int ri = rr * 2 + h;
            int sg = sseg[b * BR + ri];
            if (sg != cur) {
                if (cur >= 0) {
                    float* dst = (float*)g_sums4 + ((size_t)cur << 9) + (c128 << 2);
                    atomicAdd(dst + 0, acc.x);
                    atomicAdd(dst + 1, acc.y);
                    atomicAdd(dst + 2, acc.z);
                    atomicAdd(dst + 3, acc.w);
                    float ws = ssq;
                    #pragma unroll
                    for (int o = 16; o > 0; o >>= 1)
                        ws += __shfl_down_sync(0xffffffffu, ws, o);
                    if (lane == 0) atomicAdd(&g_ssq[cur], ws);
                }
                acc = make_float4(0.f, 0.f, 0.f, 0.f);
                ssq = 0.f;
                cur = sg;
            }
            if (sg >= 0) {
                float4 v = *(const float4*)(bp + (size_t)ri * DDIM);
                acc.x += v.x; acc.y += v.y; acc.z += v.z; acc.w += v.w;
                ssq += v.x * v.x + v.y * v.y + v.z * v.z + v.w * v.w;
            }
        }
        int nxt = b + 3;
        if (nxt < NBATCH) {
            #pragma unroll
            for (int rr = 0; rr < BR / 2; ++rr) {
                int ri = rr * 2 + h;
                const float* src = fbase + ((size_t)sidx[nxt * BR + ri] << 9);
                cp_async16(ring_base + (uint32_t)((nxt & (NB - 1)) * BR + ri) * ROWB, src);
            }
            cp_commit();
        }
    }
    if (cur >= 0) {
        float* dst = (float*)g_sums4 + ((size_t)cur << 9) + (c128 << 2);
        atomicAdd(dst + 0, acc.x);
        atomicAdd(dst + 1, acc.y);
        atomicAdd(dst + 2, acc.z);
        atomicAdd(dst + 3, acc.w);
        float ws = ssq;
        #pragma unroll
        for (int o = 16; o > 0; o >>= 1)
            ws += __shfl_down_sync(0xffffffffu, ws, o);
        if (lane == 0) atomicAdd(&g_ssq[cur], ws);
    }

    grid_bar(3);

    // ---- phase 4: pass2 (one warp per group) + self-clean read state ----
    int w = t >> 5;   // 8 warps
    for (int gidx = w * GRID_STREAM + bid; gidx < NGROUP; gidx += 8 * GRID_STREAM) {
        double nn = 0.0;
        #pragma unroll
        for (int j = 0; j < 4; ++j) {
            float4 v = g_sums4[(size_t)gidx * 128 + lane + 32 * j];
            nn += (double)v.x * v.x + (double)v.y * v.y +
                  (double)v.z * v.z + (double)v.w * v.w;
        }
        // zero for next replay (written after read; L2 traffic, overlapped)
        float4 z = make_float4(0.f, 0.f, 0.f, 0.f);
        #pragma unroll
        for (int j = 0; j < 4; ++j)
            g_sums4[(size_t)gidx * 128 + lane + 32 * j] = z;
        #pragma unroll
        for (int o = 16; o > 0; o >>= 1)
            nn += __shfl_down_sync(0xffffffffu, nn, o);
        if (lane == 0) {
            int cnt = g_cnt[gidx];
            double den = (cnt > 0) ? (double)cnt : 1.0;
            g_gm[gidx] = ((double)g_ssq[gidx] - nn / den) / den;
            g_ssq[gidx] = 0.f;
            g_cnt[gidx] = 0;
        }
    }

    // ---- last-CTA finalize (ticket; scratch aliased onto dead ring) ----
    __shared__ int s_last;
    __threadfence();
    __syncthreads();
    if (t == 0)
        s_last = (atomicAdd(&g_fin_done, 1) == GRID_STREAM - 1) ? 1 : 0;
    __syncthreads();
    if (!s_last) return;
    __threadfence();

    double* fsum = (double*)sm;                                   // 8 KB
    int*    fcnt = (int*)(sm + NUM_DEMOG * TS * sizeof(double));  // 4 KB

    double lsum[NUM_DEMOG] = {0.0, 0.0, 0.0, 0.0};
    int    lcnt[NUM_DEMOG] = {0, 0, 0, 0};
    for (int gg = t; gg < NGROUP; gg += TS) {
        if (g_off[gg + 1] - g_off[gg] > 0) {   // presence from offsets (cnt already zeroed)
            int d = gg >> 9;
            lsum[d] += g_gm[gg];
            lcnt[d] += 1;
        }
    }
    #pragma unroll
    for (int d = 0; d < NUM_DEMOG; ++d) {
        fsum[d * TS + t] = lsum[d];
        fcnt[d * TS + t] = lcnt[d];
    }
    __syncthreads();
    #pragma unroll
    for (int s = TS / 2; s > 0; s >>= 1) {
        if (t < s) {
            #pragma unroll
            for (int d = 0; d < NUM_DEMOG; ++d) {
                fsum[d * TS + t] += fsum[d * TS + t + s];
                fcnt[d * TS + t] += fcnt[d * TS + t + s];
            }
        }
        __syncthreads();
    }
    if (t == 0) {
        double intra[NUM_DEMOG];
        double mu = 0.0;
        #pragma unroll
        for (int d = 0; d < NUM_DEMOG; ++d) {
            int np = fcnt[d * TS] > 0 ? fcnt[d * TS] : 1;
            intra[d] = fsum[d * TS] / (double)np;
            mu += intra[d];
        }
        mu /= (double)NUM_DEMOG;
        double loss = 0.0;
        #pragma unroll
        for (int d = 0; d < NUM_DEMOG; ++d) loss += fabs(intra[d] - mu);
        loss /= (double)NUM_DEMOG;
        out[0] = (float)loss;

        // reset barrier counters + ticket for next graph replay
        g_bar[0] = 0; g_bar[1] = 0; g_bar[2] = 0; g_bar[3] = 0;
        g_fin_done = 0;
        __threadfence();
    }
}

extern "C" void kernel_launch(void* const* d_in, const int* in_sizes, int n_in,
                              void* d_out, int out_size) {
    const float* feats  = (const float*)d_in[0];
    const void*  labels = d_in[1];
    const void*  demog  = d_in[2];
    float* out = (float*)d_out;

    const int smem_total = NB * BR * ROWB + 2 * CHUNK_PAD * (int)sizeof(int) + 16 * (int)sizeof(int) + 128;
    cudaFuncSetAttribute(k_all, cudaFuncAttributeMaxDynamicSharedMemorySize, smem_total);

    k_all<<<GRID_STREAM, TS, smem_total>>>(feats, labels, demog, out);
}